// round 6
// baseline (speedup 1.0000x reference)
#include <cuda_runtime.h>

#define NN   8192
#define NE   131072
#define NB   256
#define NHF  128
#define FIN  64
#define H3   384
#define D6   768
#define D12  1536
#define G4   3072
#define SMAXSEG 512
#define SMAX 96        // max batch segment for interact P (mean 32, sd 5.6)

// ---------------- scratch ----------------
__device__ __align__(16) float g_h[2][NN * H3];
__device__ __align__(16) float g_x[2][NN * D6];
__device__ __align__(16) float g_xw[2][NN * NHF];
__device__ float g_deg[2][NN];
__device__ int   g_cnt[2][NN];
__device__ int   g_cursor[2][NN];
__device__ int   g_rowptr[2][NN + 1];
__device__ int   g_csrc[2][NE];
__device__ float g_cnrm[2][NE];
__device__ float g_dinv[2][NN];
__device__ int   g_starts[2][NB + 1];
__device__ float g_cvec[G4];
__device__ __align__(16) float g_rb[2][NB * D6];
__device__ __align__(16) float g_gates[2][NB * G4];
__device__ __align__(16) float g_z[NB * G4];
__device__ __align__(16) float g_z1pre[NB * 256];
__device__ __align__(16) float g_z2[NB * 128];

__device__ __forceinline__ float wredsum(float v) {
#pragma unroll
    for (int o = 16; o; o >>= 1) v += __shfl_xor_sync(0xffffffffu, v, o);
    return v;
}
__device__ __forceinline__ float sgm(float x) { return 1.f / (1.f + expf(-x)); }

// ---------------- CSR build ----------------
__global__ void k_prep() {
    int i = blockIdx.x * blockDim.x + threadIdx.x;
    if (i < 2 * NN) {
        int g = i >> 13, n = i & (NN - 1);
        g_cnt[g][n] = 0;
        g_deg[g][n] = 0.f;
    }
}
__global__ void k_count(const int* __restrict__ ei1, const float* __restrict__ ew1,
                        const int* __restrict__ ei2, const float* __restrict__ ew2) {
    int g = blockIdx.y;
    const int* ei = g ? ei2 : ei1;
    const float* ew = g ? ew2 : ew1;
    int e = blockIdx.x * blockDim.x + threadIdx.x;
    if (e < NE) {
        int d = ei[NE + e];
        atomicAdd(&g_cnt[g][d], 1);
        atomicAdd(&g_deg[g][d], ew[e]);
    }
}
// scan only: cnt -> rowptr/cursor (grid 2, 1024 thr)
__global__ void k_scan() {
    __shared__ int wsum[32];
    int g = blockIdx.x;
    int t = threadIdx.x, lane = t & 31, w = t >> 5;
    int base = t * 8;
    int loc[8], s = 0;
#pragma unroll
    for (int i = 0; i < 8; i++) { loc[i] = s; s += g_cnt[g][base + i]; }
    int x = s;
#pragma unroll
    for (int o = 1; o < 32; o <<= 1) {
        int y = __shfl_up_sync(0xffffffffu, x, o);
        if (lane >= o) x += y;
    }
    if (lane == 31) wsum[w] = x;
    __syncthreads();
    if (w == 0) {
        int y = wsum[lane];
#pragma unroll
        for (int o = 1; o < 32; o <<= 1) {
            int z = __shfl_up_sync(0xffffffffu, y, o);
            if (lane >= o) y += z;
        }
        wsum[lane] = y;
    }
    __syncthreads();
    int off = x - s + ((w > 0) ? wsum[w - 1] : 0);
#pragma unroll
    for (int i = 0; i < 8; i++) {
        g_rowptr[g][base + i] = off + loc[i];
        g_cursor[g][base + i] = off + loc[i];
    }
    if (t == 1023) g_rowptr[g][NN] = wsum[31];
}
// dinv + segment starts, fully parallel (grid 32 x 2)
__global__ void k_startsdinv(const int* __restrict__ b1, const int* __restrict__ b2) {
    int g = blockIdx.y;
    int n = blockIdx.x * blockDim.x + threadIdx.x;
    if (n >= NN) return;
    g_dinv[g][n] = rsqrtf(g_deg[g][n] + 1.0f);
    const int* batch = g ? b2 : b1;
    int b = batch[n];
    if (n == 0) {
        for (int bb = 0; bb <= b; bb++) g_starts[g][bb] = 0;
    } else {
        int pb = batch[n - 1];
        if (pb != b) for (int bb = pb + 1; bb <= b; bb++) g_starts[g][bb] = n;
    }
    if (n == NN - 1) for (int bb = b + 1; bb <= NB; bb++) g_starts[g][bb] = NN;
}
__global__ void k_fill(const int* __restrict__ ei1, const float* __restrict__ ew1,
                       const int* __restrict__ ei2, const float* __restrict__ ew2) {
    int g = blockIdx.y;
    const int* ei = g ? ei2 : ei1;
    const float* ew = g ? ew2 : ew1;
    int e = blockIdx.x * blockDim.x + threadIdx.x;
    if (e >= NE) return;
    int s = ei[e], d = ei[NE + e];
    int pos = atomicAdd(&g_cursor[g][d], 1);
    g_csrc[g][pos] = s;
    g_cnrm[g][pos] = g_dinv[g][s] * ew[e] * g_dinv[g][d];
}

// ---------------- generic 64x128-tile GEMM body, 4x8 micro, double buffer ----------------
// C[64 x 128 tile] (+epi) = A[rows, K] @ B ; BMODE 0: B[k*ldb+n] ; 1: B[n*ldb+k]
// EPI 0: store ; 1: store + cvec[col] ; 2: atomicAdd
template<int BMODE, int EPI>
__device__ __forceinline__ void gemm_body(
    const float* __restrict__ A, int lda,
    const float* __restrict__ B, int ldb,
    float* __restrict__ C, int ldc,
    int K, int kBase, const float* __restrict__ cvec)
{
    __shared__ float As[2][16][64];
    __shared__ float Bs[2][16][128];
    int tid = threadIdx.x, tx = tid & 15, ty = tid >> 4;
    int colBase = blockIdx.x * 128, rowBase = blockIdx.y * 64;
    float acc[4][8] = {};
    int nk = K / 16;

    auto load = [&](int buf, int k0) {
#pragma unroll
        for (int l = 0; l < 4; l++) {
            int idx = tid + l * 256;
            int m = idx >> 4, kk = idx & 15;
            As[buf][kk][m] = A[(size_t)(rowBase + m) * lda + k0 + kk];
        }
        if (BMODE == 0) {
#pragma unroll
            for (int l = 0; l < 8; l++) {
                int idx = tid + l * 256;
                int kk = idx >> 7, n = idx & 127;
                Bs[buf][kk][n] = B[(size_t)(k0 + kk) * ldb + colBase + n];
            }
        } else {
#pragma unroll
            for (int l = 0; l < 8; l++) {
                int idx = tid + l * 256;
                int n = idx >> 4, kk = idx & 15;
                Bs[buf][kk][n] = B[(size_t)(colBase + n) * ldb + k0 + kk];
            }
        }
    };

    load(0, kBase);
    __syncthreads();
    for (int t = 0; t < nk; t++) {
        int cur = t & 1;
        if (t + 1 < nk) load(cur ^ 1, kBase + (t + 1) * 16);
#pragma unroll
        for (int kk = 0; kk < 16; kk++) {
            float4 av = *(const float4*)&As[cur][kk][ty * 4];
            float4 b0 = *(const float4*)&Bs[cur][kk][tx * 8];
            float4 b1 = *(const float4*)&Bs[cur][kk][tx * 8 + 4];
            float a[4] = { av.x, av.y, av.z, av.w };
            float bb[8] = { b0.x, b0.y, b0.z, b0.w, b1.x, b1.y, b1.z, b1.w };
#pragma unroll
            for (int i = 0; i < 4; i++)
#pragma unroll
                for (int j = 0; j < 8; j++) acc[i][j] += a[i] * bb[j];
        }
        __syncthreads();
    }
#pragma unroll
    for (int i = 0; i < 4; i++) {
        int row = rowBase + ty * 4 + i;
#pragma unroll
        for (int j = 0; j < 8; j++) {
            int col = colBase + tx * 8 + j;
            float v = acc[i][j];
            if (EPI == 1) v += cvec[col];
            if (EPI == 2) atomicAdd(&C[(size_t)row * ldc + col], v);
            else          C[(size_t)row * ldc + col] = v;
        }
    }
}

// xw: grid (1, 128, 2)
__global__ void __launch_bounds__(256) k_xw(const float* __restrict__ f1,
                                            const float* __restrict__ f2,
                                            int layer, const float* __restrict__ W) {
    int g = blockIdx.z;
    const float* A; int lda, K;
    if (layer == 0) { A = g ? f2 : f1; lda = FIN; K = FIN; }
    else            { A = g_h[g] + (layer - 1) * NHF; lda = H3; K = NHF; }
    gemm_body<0, 0>(A, lda, W, NHF, g_xw[g], NHF, K, 0, nullptr);
}
// gates2: grid (24, 4, 2)
__global__ void __launch_bounds__(256) k_gates2(const float* __restrict__ Wih) {
    int g = blockIdx.z;
    gemm_body<1, 1>(g_rb[g], D6, Wih + D6, D12, g_gates[g], G4, D6, 0, g_cvec);
}
// mlp1: grid (2, 4, 12), split-K 256
__global__ void __launch_bounds__(256) k_mlp1(const float* __restrict__ Wp1) {
    int kBase = blockIdx.z * 256;
    gemm_body<1, 2>(g_z, G4, Wp1, G4, g_z1pre, 256, 256, kBase, nullptr);
}

// ---------------- fused GCN aggregation ----------------
__global__ void k_gather(int off, const float* __restrict__ bias) {
    int g = blockIdx.y;
    int n = blockIdx.x * 8 + (threadIdx.x >> 5);
    int lane = threadIdx.x & 31;
    if (n >= NN) return;
    const float4* xw4 = (const float4*)g_xw[g];
    float di = g_dinv[g][n];
    float sn = di * di;
    float4 bb = ((const float4*)bias)[lane];
    float4 sv = xw4[(size_t)n * 32 + lane];
    float ax = bb.x + sn * sv.x, ay = bb.y + sn * sv.y;
    float az = bb.z + sn * sv.z, aw = bb.w + sn * sv.w;
    int e0 = g_rowptr[g][n], e1 = g_rowptr[g][n + 1];
    for (int e = e0; e < e1; e++) {
        int s = g_csrc[g][e];
        float nm = g_cnrm[g][e];
        float4 v = xw4[(size_t)s * 32 + lane];
        ax += nm * v.x; ay += nm * v.y; az += nm * v.z; aw += nm * v.w;
    }
    ax = (ax >= 0.f) ? ax : 0.2f * ax;
    ay = (ay >= 0.f) ? ay : 0.2f * ay;
    az = (az >= 0.f) ? az : 0.2f * az;
    aw = (aw >= 0.f) ? aw : 0.2f * aw;
    float4* o = (float4*)(g_h[g] + (size_t)n * H3 + off);
    o[lane] = make_float4(ax, ay, az, aw);
}

// ---------------- L2 normalize ----------------
__global__ void k_l2() {
    int g = blockIdx.y;
    int warp = blockIdx.x * 8 + (threadIdx.x >> 5);
    int lane = threadIdx.x & 31;
    if (warp >= NN) return;
    const float* hr = g_h[g] + (size_t)warp * H3;
    float ss = 0.f;
#pragma unroll
    for (int t = 0; t < 12; t++) { float v = hr[lane + 32 * t]; ss += v * v; }
    ss = wredsum(ss);
    float inv = 1.f / fmaxf(sqrtf(ss), 1e-12f);
    float* xr = g_x[g] + (size_t)warp * D6;
#pragma unroll
    for (int t = 0; t < 12; t++) xr[lane + 32 * t] = hr[lane + 32 * t] * inv;
}

// ---------------- interaction: two-phase, P shared by both directions ----------------
__global__ void __launch_bounds__(256) k_interact() {
    __shared__ float P[SMAX][SMAX + 1];
    int b = blockIdx.x;
    int s1 = g_starts[0][b], e1 = g_starts[0][b + 1];
    int s2 = g_starts[1][b], e2 = g_starts[1][b + 1];
    int n1 = min(e1 - s1, SMAX), n2 = min(e2 - s2, SMAX);
    int lane = threadIdx.x & 31, w = threadIdx.x >> 5;
    // phase 1: P[i][j] = ns_i . nv_j (warp per i)
    for (int i = w; i < n1; i += 8) {
        const float* sr = g_x[0] + (size_t)(s1 + i) * D6;
        float sv[12];
#pragma unroll
        for (int q = 0; q < 12; q++) sv[q] = sr[lane + 32 * q];
        for (int j = 0; j < n2; j++) {
            const float* vr = g_x[1] + (size_t)(s2 + j) * D6;
            float p = 0.f;
#pragma unroll
            for (int q = 0; q < 12; q++) p += sv[q] * vr[lane + 32 * q];
            p = wredsum(p);
            if (lane == 0) P[i][j] = p;
        }
    }
    __syncthreads();
    // phase 2: r1_i = sum_j P[i][j] nv_j ; r2_j = sum_i P[i][j] ns_i
    int tot = n1 + n2;
    for (int t = w; t < tot; t += 8) {
        const float* oth;
        float* out;
        int row, obase, ocnt;
        bool first = (t < n1);
        if (first) { row = s1 + t;        oth = g_x[1]; obase = s2; ocnt = n2; out = g_x[0]; }
        else       { row = s2 + (t - n1); oth = g_x[0]; obase = s1; ocnt = n1; out = g_x[1]; }
        float acc[12];
#pragma unroll
        for (int q = 0; q < 12; q++) acc[q] = 0.f;
        for (int jj = 0; jj < ocnt; jj++) {
            float wv = first ? P[t][jj] : P[jj][t - n1];
            const float* vr = oth + (size_t)(obase + jj) * D6;
#pragma unroll
            for (int q = 0; q < 12; q++) acc[q] += wv * vr[lane + 32 * q];
        }
        float* orow = out + (size_t)row * D6 + H3;
#pragma unroll
        for (int q = 0; q < 12; q++) orow[lane + 32 * q] = acc[q];
    }
}

// ---------------- cvec + z1pre zero ----------------
__global__ void k_cvec(const float* __restrict__ Wih, const float* __restrict__ Whh,
                       const float* __restrict__ bih, const float* __restrict__ bhh) {
    __shared__ float shv[D6];
    int tid = threadIdx.x, lane = tid & 31, w = tid >> 5;
    for (int j = tid; j < D6; j += 256) {
        float gi = bih[j] + bhh[j];
        float gg = bih[2 * D6 + j] + bhh[2 * D6 + j];
        float go = bih[3 * D6 + j] + bhh[3 * D6 + j];
        float c = sgm(gi) * tanhf(gg);
        shv[j] = sgm(go) * tanhf(c);
    }
    if (blockIdx.x < 256) g_z1pre[blockIdx.x * 256 + tid] = 0.f;
    __syncthreads();
    int gout = blockIdx.x * 8 + w;
    const float* wi = Wih + (size_t)gout * D12;
    const float* wh = Whh + (size_t)gout * D6;
    float p = 0.f;
#pragma unroll
    for (int t = 0; t < 24; t++) {
        int k = lane + 32 * t;
        p += shv[k] * (wi[k] + wh[k]);
    }
    p = wredsum(p);
    if (lane == 0) g_cvec[gout] = bih[gout] + bhh[gout] + p;
}

// ---------------- fused attention step 1 ----------------
__global__ void k_attn1(const float* __restrict__ bih, const float* __restrict__ bhh) {
    __shared__ float hq[D6];
    __shared__ float sc[SMAXSEG];
    __shared__ float red[256];
    int g = blockIdx.y, b = blockIdx.x;
    int tid = threadIdx.x, lane = tid & 31, w = tid >> 5;
    for (int j = tid; j < D6; j += 256) {
        float gi = bih[j] + bhh[j];
        float gg = bih[2 * D6 + j] + bhh[2 * D6 + j];
        float go = bih[3 * D6 + j] + bhh[3 * D6 + j];
        float c = sgm(gi) * tanhf(gg);
        hq[j] = sgm(go) * tanhf(c);
    }
    __syncthreads();
    int s = g_starts[g][b], e = g_starts[g][b + 1], cnt = e - s;
    float* rout = g_rb[g] + (size_t)b * D6;
    if (cnt <= 0) {
        for (int j = tid; j < D6; j += 256) rout[j] = 0.f;
        return;
    }
    const float* x = g_x[g];
    for (int t = w; t < cnt; t += 8) {
        const float* xr = x + (size_t)(s + t) * D6;
        float p = 0.f;
#pragma unroll
        for (int q = 0; q < 24; q++) p += xr[lane + 32 * q] * hq[lane + 32 * q];
        p = wredsum(p);
        if (lane == 0) sc[t] = p;
    }
    __syncthreads();
    float lm = -3.4e38f;
    for (int t = tid; t < cnt; t += 256) lm = fmaxf(lm, sc[t]);
    red[tid] = lm; __syncthreads();
    for (int o = 128; o > 0; o >>= 1) { if (tid < o) red[tid] = fmaxf(red[tid], red[tid + o]); __syncthreads(); }
    float m = red[0]; __syncthreads();
    float ls = 0.f;
    for (int t = tid; t < cnt; t += 256) { float ev = expf(sc[t] - m); sc[t] = ev; ls += ev; }
    red[tid] = ls; __syncthreads();
    for (int o = 128; o > 0; o >>= 1) { if (tid < o) red[tid] += red[tid + o]; __syncthreads(); }
    float inv = 1.f / red[0]; __syncthreads();
    float a0 = 0.f, a1 = 0.f, a2 = 0.f;
    for (int t = 0; t < cnt; t++) {
        float wv = sc[t];
        const float* xr = x + (size_t)(s + t) * D6;
        a0 += wv * xr[tid];
        a1 += wv * xr[tid + 256];
        a2 += wv * xr[tid + 512];
    }
    rout[tid] = a0 * inv;
    rout[tid + 256] = a1 * inv;
    rout[tid + 512] = a2 * inv;
}

// ---------------- fused attention step 2 (lstm2 + attention) ----------------
__global__ void k_attn2(const float* __restrict__ bih, const float* __restrict__ bhh) {
    __shared__ float hq[D6];
    __shared__ float sc[SMAXSEG];
    __shared__ float red[256];
    int g = blockIdx.y, b = blockIdx.x;
    int tid = threadIdx.x, lane = tid & 31, w = tid >> 5;
    const float* gt = g_gates[g] + (size_t)b * G4;
    float* zb = g_z + (size_t)b * G4 + (g ? D12 : 0);
    for (int j = tid; j < D6; j += 256) {
        float gi1 = bih[j] + bhh[j];
        float gg1 = bih[2 * D6 + j] + bhh[2 * D6 + j];
        float cv = sgm(gi1) * tanhf(gg1);
        float gi = gt[j], gf = gt[D6 + j], gg = gt[2 * D6 + j], go = gt[3 * D6 + j];
        float c = sgm(gf) * cv + sgm(gi) * tanhf(gg);
        float h = sgm(go) * tanhf(c);
        hq[j] = h;
        zb[j] = h;
    }
    __syncthreads();
    int s = g_starts[g][b], e = g_starts[g][b + 1], cnt = e - s;
    float* rout = zb + D6;
    if (cnt <= 0) {
        for (int j = tid; j < D6; j += 256) rout[j] = 0.f;
        return;
    }
    const float* x = g_x[g];
    for (int t = w; t < cnt; t += 8) {
        const float* xr = x + (size_t)(s + t) * D6;
        float p = 0.f;
#pragma unroll
        for (int q = 0; q < 24; q++) p += xr[lane + 32 * q] * hq[lane + 32 * q];
        p = wredsum(p);
        if (lane == 0) sc[t] = p;
    }
    __syncthreads();
    float lm = -3.4e38f;
    for (int t = tid; t < cnt; t += 256) lm = fmaxf(lm, sc[t]);
    red[tid] = lm; __syncthreads();
    for (int o = 128; o > 0; o >>= 1) { if (tid < o) red[tid] = fmaxf(red[tid], red[tid + o]); __syncthreads(); }
    float m = red[0]; __syncthreads();
    float ls = 0.f;
    for (int t = tid; t < cnt; t += 256) { float ev = expf(sc[t] - m); sc[t] = ev; ls += ev; }
    red[tid] = ls; __syncthreads();
    for (int o = 128; o > 0; o >>= 1) { if (tid < o) red[tid] += red[tid + o]; __syncthreads(); }
    float inv = 1.f / red[0]; __syncthreads();
    float a0 = 0.f, a1 = 0.f, a2 = 0.f;
    for (int t = 0; t < cnt; t++) {
        float wv = sc[t];
        const float* xr = x + (size_t)(s + t) * D6;
        a0 += wv * xr[tid];
        a1 += wv * xr[tid + 256];
        a2 += wv * xr[tid + 512];
    }
    rout[tid] = a0 * inv;
    rout[tid + 256] = a1 * inv;
    rout[tid + 512] = a2 * inv;
}

// ---------------- MLP tail ----------------
__global__ void k_mlp2(const float* __restrict__ bp1,
                       const float* __restrict__ Wp2, const float* __restrict__ bp2) {
    int gw = (blockIdx.x * blockDim.x + threadIdx.x) >> 5;
    int lane = threadIdx.x & 31;
    if (gw >= NB * 128) return;
    int b = gw >> 7, o = gw & 127;
    const float* zp = g_z1pre + (size_t)b * 256;
    const float* wr = Wp2 + (size_t)o * 256;
    float p = 0.f;
#pragma unroll
    for (int k = lane; k < 256; k += 32) {
        float zv = fmaxf(zp[k] + bp1[k], 0.f);
        p += zv * wr[k];
    }
    p = wredsum(p);
    if (lane == 0) g_z2[(size_t)b * 128 + o] = fmaxf(p + bp2[o], 0.f);
}
__global__ void k_final(const float* __restrict__ Wp3, const float* __restrict__ bp3,
                        float* __restrict__ out) {
    int b = blockIdx.x * blockDim.x + threadIdx.x;
    if (b >= NB) return;
    float p = bp3[0];
#pragma unroll 16
    for (int k = 0; k < 128; k++) p += g_z2[(size_t)b * 128 + k] * Wp3[k];
    out[b] = 1.f / (1.f + expf(-p));
}

// ---------------- launch sequence ----------------
extern "C" void kernel_launch(void* const* d_in, const int* in_sizes, int n_in,
                              void* d_out, int out_size) {
    const float* f1 = (const float*)d_in[0];
    const float* f2 = (const float*)d_in[1];
    const float* ea1 = (const float*)d_in[2];
    const float* ea2 = (const float*)d_in[3];
    const float* W[3]  = { (const float*)d_in[4], (const float*)d_in[6], (const float*)d_in[8] };
    const float* bW[3] = { (const float*)d_in[5], (const float*)d_in[7], (const float*)d_in[9] };
    const float* Wih = (const float*)d_in[10];
    const float* bih = (const float*)d_in[11];
    const float* Whh = (const float*)d_in[12];
    const float* bhh = (const float*)d_in[13];
    const float* Wp1 = (const float*)d_in[14];
    const float* bp1 = (const float*)d_in[15];
    const float* Wp2 = (const float*)d_in[16];
    const float* bp2 = (const float*)d_in[17];
    const float* Wp3 = (const float*)d_in[18];
    const float* bp3 = (const float*)d_in[19];
    const int* ei1 = (const int*)d_in[20];
    const int* ei2 = (const int*)d_in[21];
    const int* b1 = (const int*)d_in[22];
    const int* b2 = (const int*)d_in[23];
    float* out = (float*)d_out;

    static cudaStream_t s1 = (cudaStream_t)0;
    static cudaEvent_t evA, evB;
    static bool inited = false;
    if (!inited) {
        cudaStreamCreateWithFlags(&s1, cudaStreamNonBlocking);
        cudaEventCreateWithFlags(&evA, cudaEventDisableTiming);
        cudaEventCreateWithFlags(&evB, cudaEventDisableTiming);
        inited = true;
    }
    cudaStream_t s0 = (cudaStream_t)0;
    const int T = 256;

    // fork: CSR build on side stream, overlapped with cvec + layer-0 GEMM
    cudaEventRecord(evA, s0);
    cudaStreamWaitEvent(s1, evA, 0);
    k_prep<<<2 * NN / T, T, 0, s1>>>();
    k_count<<<dim3(NE / T, 2), T, 0, s1>>>(ei1, ea1, ei2, ea2);
    k_scan<<<2, 1024, 0, s1>>>();
    k_startsdinv<<<dim3(NN / T, 2), T, 0, s1>>>(b1, b2);
    k_fill<<<dim3(NE / T, 2), T, 0, s1>>>(ei1, ea1, ei2, ea2);
    cudaEventRecord(evB, s1);

    k_cvec<<<G4 / 8, T, 0, s0>>>(Wih, Whh, bih, bhh);
    k_xw<<<dim3(1, NN / 64, 2), T, 0, s0>>>(f1, f2, 0, W[0]);

    // join: gather needs CSR
    cudaStreamWaitEvent(s0, evB, 0);
    k_gather<<<dim3(NN / 8, 2), T, 0, s0>>>(0, bW[0]);
    for (int l = 1; l < 3; l++) {
        k_xw<<<dim3(1, NN / 64, 2), T, 0, s0>>>(f1, f2, l, W[l]);
        k_gather<<<dim3(NN / 8, 2), T, 0, s0>>>(l * NHF, bW[l]);
    }
    k_l2<<<dim3(NN / 8, 2), T, 0, s0>>>();
    k_interact<<<NB, T, 0, s0>>>();

    k_attn1<<<dim3(NB, 2), T, 0, s0>>>(bih, bhh);
    k_gates2<<<dim3(G4 / 128, NB / 64, 2), T, 0, s0>>>(Wih);
    k_attn2<<<dim3(NB, 2), T, 0, s0>>>(bih, bhh);

    k_mlp1<<<dim3(2, 4, 12), T, 0, s0>>>(Wp1);
    k_mlp2<<<(NB * 128 * 32) / T, T, 0, s0>>>(bp1, Wp2, bp2);
    k_final<<<1, T, 0, s0>>>(Wp3, bp3, out);
}

// round 7
// speedup vs baseline: 1.6081x; 1.6081x over previous
#include <cuda_runtime.h>

#define NN   8192
#define NE   131072
#define NB   256
#define NHF  128
#define FIN  64
#define H3   384
#define D6   768
#define D12  1536
#define G4   3072
#define SMAXSEG 512

// ---------------- scratch ----------------
__device__ __align__(16) float g_h[2][NN * H3];
__device__ __align__(16) float g_x[2][NN * D6];
__device__ __align__(16) float g_xw[2][NN * NHF];
__device__ float g_deg[2][NN];
__device__ int   g_cnt[2][NN];
__device__ int   g_cursor[2][NN];
__device__ int   g_rowptr[2][NN + 1];
__device__ int   g_csrc[2][NE];
__device__ float g_cnrm[2][NE];
__device__ float g_dinv[2][NN];
__device__ int   g_starts[2][NB + 1];
__device__ float g_cvec[G4];
__device__ __align__(16) float g_rb[2][NB * D6];
__device__ __align__(16) float g_gates[2][NB * G4];
__device__ __align__(16) float g_z[NB * G4];
__device__ __align__(16) float g_z1pre[NB * 256];
__device__ __align__(16) float g_z2[NB * 128];

__device__ __forceinline__ float wredsum(float v) {
#pragma unroll
    for (int o = 16; o; o >>= 1) v += __shfl_xor_sync(0xffffffffu, v, o);
    return v;
}
__device__ __forceinline__ float sgm(float x) { return 1.f / (1.f + expf(-x)); }

// ---------------- CSR build ----------------
__global__ void k_prep() {
    int i = blockIdx.x * blockDim.x + threadIdx.x;
    if (i < 2 * NN) {
        int g = i >> 13, n = i & (NN - 1);
        g_cnt[g][n] = 0;
        g_deg[g][n] = 0.f;
    }
}
__global__ void k_count(const int* __restrict__ ei1, const float* __restrict__ ew1,
                        const int* __restrict__ ei2, const float* __restrict__ ew2) {
    int g = blockIdx.y;
    const int* ei = g ? ei2 : ei1;
    const float* ew = g ? ew2 : ew1;
    int e = blockIdx.x * blockDim.x + threadIdx.x;
    if (e < NE) {
        int d = ei[NE + e];
        atomicAdd(&g_cnt[g][d], 1);
        atomicAdd(&g_deg[g][d], ew[e]);
    }
}
// scan only (grid 2, 1024 thr, warp-shuffle)
__global__ void k_scan() {
    __shared__ int wsum[32];
    int g = blockIdx.x;
    int t = threadIdx.x, lane = t & 31, w = t >> 5;
    int base = t * 8;
    int loc[8], s = 0;
#pragma unroll
    for (int i = 0; i < 8; i++) { loc[i] = s; s += g_cnt[g][base + i]; }
    int x = s;
#pragma unroll
    for (int o = 1; o < 32; o <<= 1) {
        int y = __shfl_up_sync(0xffffffffu, x, o);
        if (lane >= o) x += y;
    }
    if (lane == 31) wsum[w] = x;
    __syncthreads();
    if (w == 0) {
        int y = wsum[lane];
#pragma unroll
        for (int o = 1; o < 32; o <<= 1) {
            int z = __shfl_up_sync(0xffffffffu, y, o);
            if (lane >= o) y += z;
        }
        wsum[lane] = y;
    }
    __syncthreads();
    int off = x - s + ((w > 0) ? wsum[w - 1] : 0);
#pragma unroll
    for (int i = 0; i < 8; i++) {
        g_rowptr[g][base + i] = off + loc[i];
        g_cursor[g][base + i] = off + loc[i];
    }
    if (t == 1023) g_rowptr[g][NN] = wsum[31];
}
// dinv + segment starts (grid 32 x 2)
__global__ void k_startsdinv(const int* __restrict__ b1, const int* __restrict__ b2) {
    int g = blockIdx.y;
    int n = blockIdx.x * blockDim.x + threadIdx.x;
    if (n >= NN) return;
    g_dinv[g][n] = rsqrtf(g_deg[g][n] + 1.0f);
    const int* batch = g ? b2 : b1;
    int b = batch[n];
    if (n == 0) {
        for (int bb = 0; bb <= b; bb++) g_starts[g][bb] = 0;
    } else {
        int pb = batch[n - 1];
        if (pb != b) for (int bb = pb + 1; bb <= b; bb++) g_starts[g][bb] = n;
    }
    if (n == NN - 1) for (int bb = b + 1; bb <= NB; bb++) g_starts[g][bb] = NN;
}
__global__ void k_fill(const int* __restrict__ ei1, const float* __restrict__ ew1,
                       const int* __restrict__ ei2, const float* __restrict__ ew2) {
    int g = blockIdx.y;
    const int* ei = g ? ei2 : ei1;
    const float* ew = g ? ew2 : ew1;
    int e = blockIdx.x * blockDim.x + threadIdx.x;
    if (e >= NE) return;
    int s = ei[e], d = ei[NE + e];
    int pos = atomicAdd(&g_cursor[g][d], 1);
    g_csrc[g][pos] = s;
    g_cnrm[g][pos] = g_dinv[g][s] * ew[e] * g_dinv[g][d];
}

// ---------------- tiled GEMM (round-5 proven 64x64, 4x4): g_xw[g] = X @ W ----------------
__global__ void k_gemm_xw(const float* __restrict__ f1, const float* __restrict__ f2,
                          int layer, const float* __restrict__ W) {
    __shared__ float As[16][64];
    __shared__ float Bs[16][68];
    int g = blockIdx.z;
    const float* X;
    int ldx, K;
    if (layer == 0) { X = g ? f2 : f1; ldx = FIN; K = FIN; }
    else            { X = g_h[g] + (layer - 1) * NHF; ldx = H3; K = NHF; }
    int tid = threadIdx.x, tx = tid & 15, ty = tid >> 4;
    int colBase = blockIdx.x * 64, rowBase = blockIdx.y * 64;
    float acc[4][4] = {};
    for (int k0 = 0; k0 < K; k0 += 16) {
#pragma unroll
        for (int l = 0; l < 4; l++) {
            int idx = tid + l * 256;
            int m = idx >> 4, kk = idx & 15;
            As[kk][m] = X[(size_t)(rowBase + m) * ldx + k0 + kk];
            Bs[kk][m] = W[(size_t)(k0 + kk) * NHF + colBase + m];
        }
        __syncthreads();
#pragma unroll
        for (int kk = 0; kk < 16; kk++) {
            float av[4], bv[4];
#pragma unroll
            for (int i = 0; i < 4; i++) av[i] = As[kk][ty * 4 + i];
#pragma unroll
            for (int j = 0; j < 4; j++) bv[j] = Bs[kk][tx * 4 + j];
#pragma unroll
            for (int i = 0; i < 4; i++)
#pragma unroll
                for (int j = 0; j < 4; j++) acc[i][j] += av[i] * bv[j];
        }
        __syncthreads();
    }
#pragma unroll
    for (int i = 0; i < 4; i++)
#pragma unroll
        for (int j = 0; j < 4; j++)
            g_xw[g][(size_t)(rowBase + ty * 4 + i) * NHF + colBase + tx * 4 + j] = acc[i][j];
}

// ---------------- fused GCN aggregation ----------------
__global__ void k_gather(int off, const float* __restrict__ bias) {
    int g = blockIdx.y;
    int n = blockIdx.x * 8 + (threadIdx.x >> 5);
    int lane = threadIdx.x & 31;
    if (n >= NN) return;
    const float4* xw4 = (const float4*)g_xw[g];
    float di = g_dinv[g][n];
    float sn = di * di;
    float4 bb = ((const float4*)bias)[lane];
    float4 sv = xw4[(size_t)n * 32 + lane];
    float ax = bb.x + sn * sv.x, ay = bb.y + sn * sv.y;
    float az = bb.z + sn * sv.z, aw = bb.w + sn * sv.w;
    int e0 = g_rowptr[g][n], e1 = g_rowptr[g][n + 1];
    for (int e = e0; e < e1; e++) {
        int s = g_csrc[g][e];
        float nm = g_cnrm[g][e];
        float4 v = xw4[(size_t)s * 32 + lane];
        ax += nm * v.x; ay += nm * v.y; az += nm * v.z; aw += nm * v.w;
    }
    ax = (ax >= 0.f) ? ax : 0.2f * ax;
    ay = (ay >= 0.f) ? ay : 0.2f * ay;
    az = (az >= 0.f) ? az : 0.2f * az;
    aw = (aw >= 0.f) ? aw : 0.2f * aw;
    float4* o = (float4*)(g_h[g] + (size_t)n * H3 + off);
    o[lane] = make_float4(ax, ay, az, aw);
}

// ---------------- L2 normalize ----------------
__global__ void k_l2() {
    int g = blockIdx.y;
    int warp = blockIdx.x * 8 + (threadIdx.x >> 5);
    int lane = threadIdx.x & 31;
    if (warp >= NN) return;
    const float* hr = g_h[g] + (size_t)warp * H3;
    float ss = 0.f;
#pragma unroll
    for (int t = 0; t < 12; t++) { float v = hr[lane + 32 * t]; ss += v * v; }
    ss = wredsum(ss);
    float inv = 1.f / fmaxf(sqrtf(ss), 1e-12f);
    float* xr = g_x[g] + (size_t)warp * D6;
#pragma unroll
    for (int t = 0; t < 12; t++) xr[lane + 32 * t] = hr[lane + 32 * t] * inv;
}

// ---------------- interaction (round-5 proven: single-pass, 512 thr) ----------------
__global__ void __launch_bounds__(512) k_interact() {
    int b = blockIdx.x;
    int s1 = g_starts[0][b], e1 = g_starts[0][b + 1];
    int s2 = g_starts[1][b], e2 = g_starts[1][b + 1];
    int n1 = e1 - s1, n2 = e2 - s2, tot = n1 + n2;
    int lane = threadIdx.x & 31, w = threadIdx.x >> 5;
    for (int t = w; t < tot; t += 16) {
        const float *src, *oth;
        float* out;
        int row, obase, ocnt;
        if (t < n1) { row = s1 + t;        src = g_x[0]; oth = g_x[1]; obase = s2; ocnt = n2; out = g_x[0]; }
        else        { row = s2 + (t - n1); src = g_x[1]; oth = g_x[0]; obase = s1; ocnt = n1; out = g_x[1]; }
        const float* sr = src + (size_t)row * D6;
        float sv[12], acc[12];
#pragma unroll
        for (int q = 0; q < 12; q++) { sv[q] = sr[lane + 32 * q]; acc[q] = 0.f; }
        for (int jj = 0; jj < ocnt; jj++) {
            const float* vr = oth + (size_t)(obase + jj) * D6;
            float vv[12], p = 0.f;
#pragma unroll
            for (int q = 0; q < 12; q++) { vv[q] = vr[lane + 32 * q]; p += sv[q] * vv[q]; }
            p = wredsum(p);
#pragma unroll
            for (int q = 0; q < 12; q++) acc[q] += p * vv[q];
        }
        float* orow = out + (size_t)row * D6 + H3;
#pragma unroll
        for (int q = 0; q < 12; q++) orow[lane + 32 * q] = acc[q];
    }
}

// ---------------- cvec + z1pre zero ----------------
__global__ void k_cvec(const float* __restrict__ Wih, const float* __restrict__ Whh,
                       const float* __restrict__ bih, const float* __restrict__ bhh) {
    __shared__ float shv[D6];
    int tid = threadIdx.x, lane = tid & 31, w = tid >> 5;
    for (int j = tid; j < D6; j += 256) {
        float gi = bih[j] + bhh[j];
        float gg = bih[2 * D6 + j] + bhh[2 * D6 + j];
        float go = bih[3 * D6 + j] + bhh[3 * D6 + j];
        float c = sgm(gi) * tanhf(gg);
        shv[j] = sgm(go) * tanhf(c);
    }
    if (blockIdx.x < 256) g_z1pre[blockIdx.x * 256 + tid] = 0.f;
    __syncthreads();
    int gout = blockIdx.x * 8 + w;
    const float* wi = Wih + (size_t)gout * D12;
    const float* wh = Whh + (size_t)gout * D6;
    float p = 0.f;
#pragma unroll
    for (int t = 0; t < 24; t++) {
        int k = lane + 32 * t;
        p += shv[k] * (wi[k] + wh[k]);
    }
    p = wredsum(p);
    if (lane == 0) g_cvec[gout] = bih[gout] + bhh[gout] + p;
}

// ---------------- fused attention step 1 ----------------
__global__ void k_attn1(const float* __restrict__ bih, const float* __restrict__ bhh) {
    __shared__ float hq[D6];
    __shared__ float sc[SMAXSEG];
    __shared__ float red[256];
    int g = blockIdx.y, b = blockIdx.x;
    int tid = threadIdx.x, lane = tid & 31, w = tid >> 5;
    for (int j = tid; j < D6; j += 256) {
        float gi = bih[j] + bhh[j];
        float gg = bih[2 * D6 + j] + bhh[2 * D6 + j];
        float go = bih[3 * D6 + j] + bhh[3 * D6 + j];
        float c = sgm(gi) * tanhf(gg);
        hq[j] = sgm(go) * tanhf(c);
    }
    __syncthreads();
    int s = g_starts[g][b], e = g_starts[g][b + 1], cnt = e - s;
    float* rout = g_rb[g] + (size_t)b * D6;
    if (cnt <= 0) {
        for (int j = tid; j < D6; j += 256) rout[j] = 0.f;
        return;
    }
    const float* x = g_x[g];
    for (int t = w; t < cnt; t += 8) {
        const float* xr = x + (size_t)(s + t) * D6;
        float p = 0.f;
#pragma unroll
        for (int q = 0; q < 24; q++) p += xr[lane + 32 * q] * hq[lane + 32 * q];
        p = wredsum(p);
        if (lane == 0) sc[t] = p;
    }
    __syncthreads();
    float lm = -3.4e38f;
    for (int t = tid; t < cnt; t += 256) lm = fmaxf(lm, sc[t]);
    red[tid] = lm; __syncthreads();
    for (int o = 128; o > 0; o >>= 1) { if (tid < o) red[tid] = fmaxf(red[tid], red[tid + o]); __syncthreads(); }
    float m = red[0]; __syncthreads();
    float ls = 0.f;
    for (int t = tid; t < cnt; t += 256) { float ev = expf(sc[t] - m); sc[t] = ev; ls += ev; }
    red[tid] = ls; __syncthreads();
    for (int o = 128; o > 0; o >>= 1) { if (tid < o) red[tid] += red[tid + o]; __syncthreads(); }
    float inv = 1.f / red[0]; __syncthreads();
    float a0 = 0.f, a1 = 0.f, a2 = 0.f;
    for (int t = 0; t < cnt; t++) {
        float wv = sc[t];
        const float* xr = x + (size_t)(s + t) * D6;
        a0 += wv * xr[tid];
        a1 += wv * xr[tid + 256];
        a2 += wv * xr[tid + 512];
    }
    rout[tid] = a0 * inv;
    rout[tid + 256] = a1 * inv;
    rout[tid + 512] = a2 * inv;
}

// gates2 (round-5 proven 64x64): g_rb[g] @ WihR^T + cvec
__global__ void k_gates2(const float* __restrict__ Wih) {
    __shared__ float As[16][64];
    __shared__ float Bs[16][68];
    int g = blockIdx.z;
    int tid = threadIdx.x, tx = tid & 15, ty = tid >> 4;
    int colBase = blockIdx.x * 64, rowBase = blockIdx.y * 64;
    const float* A = g_rb[g];
    const float* B = Wih + D6;
    float acc[4][4] = {};
    for (int k0 = 0; k0 < D6; k0 += 16) {
#pragma unroll
        for (int l = 0; l < 4; l++) {
            int idx = tid + l * 256;
            int m = idx >> 4, kk = idx & 15;
            As[kk][m] = A[(size_t)(rowBase + m) * D6 + k0 + kk];
            Bs[kk][m] = B[(size_t)(colBase + m) * D12 + k0 + kk];
        }
        __syncthreads();
#pragma unroll
        for (int kk = 0; kk < 16; kk++) {
            float av[4], bv[4];
#pragma unroll
            for (int i = 0; i < 4; i++) av[i] = As[kk][ty * 4 + i];
#pragma unroll
            for (int j = 0; j < 4; j++) bv[j] = Bs[kk][tx * 4 + j];
#pragma unroll
            for (int i = 0; i < 4; i++)
#pragma unroll
                for (int j = 0; j < 4; j++) acc[i][j] += av[i] * bv[j];
        }
        __syncthreads();
    }
#pragma unroll
    for (int i = 0; i < 4; i++) {
        int row = rowBase + ty * 4 + i;
#pragma unroll
        for (int j = 0; j < 4; j++) {
            int col = colBase + tx * 4 + j;
            g_gates[g][(size_t)row * G4 + col] = acc[i][j] + g_cvec[col];
        }
    }
}

// ---------------- fused attention step 2 (lstm2 + attention) ----------------
__global__ void k_attn2(const float* __restrict__ bih, const float* __restrict__ bhh) {
    __shared__ float hq[D6];
    __shared__ float sc[SMAXSEG];
    __shared__ float red[256];
    int g = blockIdx.y, b = blockIdx.x;
    int tid = threadIdx.x, lane = tid & 31, w = tid >> 5;
    const float* gt = g_gates[g] + (size_t)b * G4;
    float* zb = g_z + (size_t)b * G4 + (g ? D12 : 0);
    for (int j = tid; j < D6; j += 256) {
        float gi1 = bih[j] + bhh[j];
        float gg1 = bih[2 * D6 + j] + bhh[2 * D6 + j];
        float cv = sgm(gi1) * tanhf(gg1);
        float gi = gt[j], gf = gt[D6 + j], gg = gt[2 * D6 + j], go = gt[3 * D6 + j];
        float c = sgm(gf) * cv + sgm(gi) * tanhf(gg);
        float h = sgm(go) * tanhf(c);
        hq[j] = h;
        zb[j] = h;
    }
    __syncthreads();
    int s = g_starts[g][b], e = g_starts[g][b + 1], cnt = e - s;
    float* rout = zb + D6;
    if (cnt <= 0) {
        for (int j = tid; j < D6; j += 256) rout[j] = 0.f;
        return;
    }
    const float* x = g_x[g];
    for (int t = w; t < cnt; t += 8) {
        const float* xr = x + (size_t)(s + t) * D6;
        float p = 0.f;
#pragma unroll
        for (int q = 0; q < 24; q++) p += xr[lane + 32 * q] * hq[lane + 32 * q];
        p = wredsum(p);
        if (lane == 0) sc[t] = p;
    }
    __syncthreads();
    float lm = -3.4e38f;
    for (int t = tid; t < cnt; t += 256) lm = fmaxf(lm, sc[t]);
    red[tid] = lm; __syncthreads();
    for (int o = 128; o > 0; o >>= 1) { if (tid < o) red[tid] = fmaxf(red[tid], red[tid + o]); __syncthreads(); }
    float m = red[0]; __syncthreads();
    float ls = 0.f;
    for (int t = tid; t < cnt; t += 256) { float ev = expf(sc[t] - m); sc[t] = ev; ls += ev; }
    red[tid] = ls; __syncthreads();
    for (int o = 128; o > 0; o >>= 1) { if (tid < o) red[tid] += red[tid + o]; __syncthreads(); }
    float inv = 1.f / red[0]; __syncthreads();
    float a0 = 0.f, a1 = 0.f, a2 = 0.f;
    for (int t = 0; t < cnt; t++) {
        float wv = sc[t];
        const float* xr = x + (size_t)(s + t) * D6;
        a0 += wv * xr[tid];
        a1 += wv * xr[tid + 256];
        a2 += wv * xr[tid + 512];
    }
    rout[tid] = a0 * inv;
    rout[tid + 256] = a1 * inv;
    rout[tid + 512] = a2 * inv;
}

// ---------------- MLP head (round-5 proven) ----------------
__global__ void k_mlp1_gemm(const float* __restrict__ Wp1) {
    __shared__ float As[16][64];
    __shared__ float Bs[16][68];
    int tid = threadIdx.x, tx = tid & 15, ty = tid >> 4;
    int colBase = blockIdx.x * 64, rowBase = blockIdx.y * 64;
    int kBase = blockIdx.z * 128;
    float acc[4][4] = {};
    for (int k0 = 0; k0 < 128; k0 += 16) {
#pragma unroll
        for (int l = 0; l < 4; l++) {
            int idx = tid + l * 256;
            int m = idx >> 4, kk = idx & 15;
            As[kk][m] = g_z[(size_t)(rowBase + m) * G4 + kBase + k0 + kk];
            Bs[kk][m] = Wp1[(size_t)(colBase + m) * G4 + kBase + k0 + kk];
        }
        __syncthreads();
#pragma unroll
        for (int kk = 0; kk < 16; kk++) {
            float av[4], bv[4];
#pragma unroll
            for (int i = 0; i < 4; i++) av[i] = As[kk][ty * 4 + i];
#pragma unroll
            for (int j = 0; j < 4; j++) bv[j] = Bs[kk][tx * 4 + j];
#pragma unroll
            for (int i = 0; i < 4; i++)
#pragma unroll
                for (int j = 0; j < 4; j++) acc[i][j] += av[i] * bv[j];
        }
        __syncthreads();
    }
#pragma unroll
    for (int i = 0; i < 4; i++)
#pragma unroll
        for (int j = 0; j < 4; j++)
            atomicAdd(&g_z1pre[(size_t)(rowBase + ty * 4 + i) * 256 + colBase + tx * 4 + j],
                      acc[i][j]);
}
__global__ void k_mlp2(const float* __restrict__ bp1,
                       const float* __restrict__ Wp2, const float* __restrict__ bp2) {
    int gw = (blockIdx.x * blockDim.x + threadIdx.x) >> 5;
    int lane = threadIdx.x & 31;
    if (gw >= NB * 128) return;
    int b = gw >> 7, o = gw & 127;
    const float* zp = g_z1pre + (size_t)b * 256;
    const float* wr = Wp2 + (size_t)o * 256;
    float p = 0.f;
#pragma unroll
    for (int k = lane; k < 256; k += 32) {
        float zv = fmaxf(zp[k] + bp1[k], 0.f);
        p += zv * wr[k];
    }
    p = wredsum(p);
    if (lane == 0) g_z2[(size_t)b * 128 + o] = fmaxf(p + bp2[o], 0.f);
}
__global__ void k_final(const float* __restrict__ Wp3, const float* __restrict__ bp3,
                        float* __restrict__ out) {
    int b = blockIdx.x * blockDim.x + threadIdx.x;
    if (b >= NB) return;
    float p = bp3[0];
#pragma unroll 16
    for (int k = 0; k < 128; k++) p += g_z2[(size_t)b * 128 + k] * Wp3[k];
    out[b] = 1.f / (1.f + expf(-p));
}

// ---------------- launch sequence ----------------
extern "C" void kernel_launch(void* const* d_in, const int* in_sizes, int n_in,
                              void* d_out, int out_size) {
    const float* f1 = (const float*)d_in[0];
    const float* f2 = (const float*)d_in[1];
    const float* ea1 = (const float*)d_in[2];
    const float* ea2 = (const float*)d_in[3];
    const float* W[3]  = { (const float*)d_in[4], (const float*)d_in[6], (const float*)d_in[8] };
    const float* bW[3] = { (const float*)d_in[5], (const float*)d_in[7], (const float*)d_in[9] };
    const float* Wih = (const float*)d_in[10];
    const float* bih = (const float*)d_in[11];
    const float* Whh = (const float*)d_in[12];
    const float* bhh = (const float*)d_in[13];
    const float* Wp1 = (const float*)d_in[14];
    const float* bp1 = (const float*)d_in[15];
    const float* Wp2 = (const float*)d_in[16];
    const float* bp2 = (const float*)d_in[17];
    const float* Wp3 = (const float*)d_in[18];
    const float* bp3 = (const float*)d_in[19];
    const int* ei1 = (const int*)d_in[20];
    const int* ei2 = (const int*)d_in[21];
    const int* b1 = (const int*)d_in[22];
    const int* b2 = (const int*)d_in[23];
    float* out = (float*)d_out;

    static cudaStream_t s1 = (cudaStream_t)0;
    static cudaEvent_t evA, evB;
    static bool inited = false;
    if (!inited) {
        cudaStreamCreateWithFlags(&s1, cudaStreamNonBlocking);
        cudaEventCreateWithFlags(&evA, cudaEventDisableTiming);
        cudaEventCreateWithFlags(&evB, cudaEventDisableTiming);
        inited = true;
    }
    cudaStream_t s0 = (cudaStream_t)0;
    const int T = 256;

    // side stream: CSR build overlapped with cvec + layer-0 GEMM on s0
    cudaEventRecord(evA, s0);
    cudaStreamWaitEvent(s1, evA, 0);
    k_prep<<<2 * NN / T, T, 0, s1>>>();
    k_count<<<dim3(NE / T, 2), T, 0, s1>>>(ei1, ea1, ei2, ea2);
    k_scan<<<2, 1024, 0, s1>>>();
    k_startsdinv<<<dim3(NN / T, 2), T, 0, s1>>>(b1, b2);
    k_fill<<<dim3(NE / T, 2), T, 0, s1>>>(ei1, ea1, ei2, ea2);
    cudaEventRecord(evB, s1);

    k_cvec<<<G4 / 8, T, 0, s0>>>(Wih, Whh, bih, bhh);
    k_gemm_xw<<<dim3(2, NN / 64, 2), T, 0, s0>>>(f1, f2, 0, W[0]);

    // join: gather needs CSR
    cudaStreamWaitEvent(s0, evB, 0);
    k_gather<<<dim3(NN / 8, 2), T, 0, s0>>>(0, bW[0]);
    for (int l = 1; l < 3; l++) {
        k_gemm_xw<<<dim3(2, NN / 64, 2), T, 0, s0>>>(f1, f2, l, W[l]);
        k_gather<<<dim3(NN / 8, 2), T, 0, s0>>>(l * NHF, bW[l]);
    }
    k_l2<<<dim3(NN / 8, 2), T, 0, s0>>>();
    k_interact<<<NB, 512, 0, s0>>>();

    k_attn1<<<dim3(NB, 2), T, 0, s0>>>(bih, bhh);
    k_gates2<<<dim3(G4 / 64, NB / 64, 2), T, 0, s0>>>(Wih);
    k_attn2<<<dim3(NB, 2), T, 0, s0>>>(bih, bhh);

    k_mlp1_gemm<<<dim3(4, 4, 24), T, 0, s0>>>(Wp1);
    k_mlp2<<<(NB * 128 * 32) / T, T, 0, s0>>>(bp1, Wp2, bp2);
    k_final<<<1, T, 0, s0>>>(Wp3, bp3, out);
}

// round 8
// speedup vs baseline: 1.6180x; 1.0061x over previous
#include <cuda_runtime.h>

#define NN   8192
#define NE   131072
#define NB   256
#define NHF  128
#define FIN  64
#define H3   384
#define D6   768
#define D12  1536
#define G4   3072
#define SMAXSEG 512

// ---------------- scratch ----------------
__device__ __align__(16) float g_h[2][NN * H3];
__device__ __align__(16) float g_x[2][NN * D6];
__device__ __align__(16) float g_xw[2][NN * NHF];
__device__ float g_deg[2][NN];
__device__ int   g_cnt[2][NN];
__device__ int   g_cursor[2][NN];
__device__ int   g_rowptr[2][NN + 1];
__device__ int   g_csrc[2][NE];
__device__ float g_cnrm[2][NE];
__device__ float g_dinv[2][NN];
__device__ int   g_starts[2][NB + 1];
__device__ float g_cvec[G4];
__device__ __align__(16) float g_rb[2][NB * D6];
__device__ __align__(16) float g_gates[2][NB * G4];
__device__ __align__(16) float g_z[NB * G4];
__device__ __align__(16) float g_z1pre[NB * 256];
__device__ __align__(16) float g_z2[NB * 128];

__device__ __forceinline__ float wredsum(float v) {
#pragma unroll
    for (int o = 16; o; o >>= 1) v += __shfl_xor_sync(0xffffffffu, v, o);
    return v;
}
__device__ __forceinline__ float sgm(float x) { return 1.f / (1.f + expf(-x)); }

// ---------------- CSR build ----------------
__global__ void k_prep() {
    int i = blockIdx.x * blockDim.x + threadIdx.x;
    if (i < 2 * NN) {
        int g = i >> 13, n = i & (NN - 1);
        g_cnt[g][n] = 0;
        g_deg[g][n] = 0.f;
    }
}
__global__ void k_count(const int* __restrict__ ei1, const float* __restrict__ ew1,
                        const int* __restrict__ ei2, const float* __restrict__ ew2) {
    int g = blockIdx.y;
    const int* ei = g ? ei2 : ei1;
    const float* ew = g ? ew2 : ew1;
    int e = blockIdx.x * blockDim.x + threadIdx.x;
    if (e < NE) {
        int d = ei[NE + e];
        atomicAdd(&g_cnt[g][d], 1);
        atomicAdd(&g_deg[g][d], ew[e]);
    }
}
__global__ void k_scan() {
    __shared__ int wsum[32];
    int g = blockIdx.x;
    int t = threadIdx.x, lane = t & 31, w = t >> 5;
    int base = t * 8;
    int loc[8], s = 0;
#pragma unroll
    for (int i = 0; i < 8; i++) { loc[i] = s; s += g_cnt[g][base + i]; }
    int x = s;
#pragma unroll
    for (int o = 1; o < 32; o <<= 1) {
        int y = __shfl_up_sync(0xffffffffu, x, o);
        if (lane >= o) x += y;
    }
    if (lane == 31) wsum[w] = x;
    __syncthreads();
    if (w == 0) {
        int y = wsum[lane];
#pragma unroll
        for (int o = 1; o < 32; o <<= 1) {
            int z = __shfl_up_sync(0xffffffffu, y, o);
            if (lane >= o) y += z;
        }
        wsum[lane] = y;
    }
    __syncthreads();
    int off = x - s + ((w > 0) ? wsum[w - 1] : 0);
#pragma unroll
    for (int i = 0; i < 8; i++) {
        g_rowptr[g][base + i] = off + loc[i];
        g_cursor[g][base + i] = off + loc[i];
    }
    if (t == 1023) g_rowptr[g][NN] = wsum[31];
}
__global__ void k_startsdinv(const int* __restrict__ b1, const int* __restrict__ b2) {
    int g = blockIdx.y;
    int n = blockIdx.x * blockDim.x + threadIdx.x;
    if (n >= NN) return;
    g_dinv[g][n] = rsqrtf(g_deg[g][n] + 1.0f);
    const int* batch = g ? b2 : b1;
    int b = batch[n];
    if (n == 0) {
        for (int bb = 0; bb <= b; bb++) g_starts[g][bb] = 0;
    } else {
        int pb = batch[n - 1];
        if (pb != b) for (int bb = pb + 1; bb <= b; bb++) g_starts[g][bb] = n;
    }
    if (n == NN - 1) for (int bb = b + 1; bb <= NB; bb++) g_starts[g][bb] = NN;
}
__global__ void k_fill(const int* __restrict__ ei1, const float* __restrict__ ew1,
                       const int* __restrict__ ei2, const float* __restrict__ ew2) {
    int g = blockIdx.y;
    const int* ei = g ? ei2 : ei1;
    const float* ew = g ? ew2 : ew1;
    int e = blockIdx.x * blockDim.x + threadIdx.x;
    if (e >= NE) return;
    int s = ei[e], d = ei[NE + e];
    int pos = atomicAdd(&g_cursor[g][d], 1);
    g_csrc[g][pos] = s;
    g_cnrm[g][pos] = g_dinv[g][s] * ew[e] * g_dinv[g][d];
}

// ---------------- tiled GEMM (64x64, 4x4; LDS.128 operand fetch) ----------------
__global__ void k_gemm_xw(const float* __restrict__ f1, const float* __restrict__ f2,
                          int layer, const float* __restrict__ W) {
    __shared__ float As[16][64];
    __shared__ float Bs[16][68];
    int g = blockIdx.z;
    const float* X;
    int ldx, K;
    if (layer == 0) { X = g ? f2 : f1; ldx = FIN; K = FIN; }
    else            { X = g_h[g] + (layer - 1) * NHF; ldx = H3; K = NHF; }
    int tid = threadIdx.x, tx = tid & 15, ty = tid >> 4;
    int colBase = blockIdx.x * 64, rowBase = blockIdx.y * 64;
    float acc[4][4] = {};
    for (int k0 = 0; k0 < K; k0 += 16) {
#pragma unroll
        for (int l = 0; l < 4; l++) {
            int idx = tid + l * 256;
            int m = idx >> 4, kk = idx & 15;
            As[kk][m] = X[(size_t)(rowBase + m) * ldx + k0 + kk];
            Bs[kk][m] = W[(size_t)(k0 + kk) * NHF + colBase + m];
        }
        __syncthreads();
#pragma unroll
        for (int kk = 0; kk < 16; kk++) {
            float4 a4 = *(const float4*)&As[kk][ty * 4];
            float4 b4 = *(const float4*)&Bs[kk][tx * 4];
            float av[4] = { a4.x, a4.y, a4.z, a4.w };
            float bv[4] = { b4.x, b4.y, b4.z, b4.w };
#pragma unroll
            for (int i = 0; i < 4; i++)
#pragma unroll
                for (int j = 0; j < 4; j++) acc[i][j] += av[i] * bv[j];
        }
        __syncthreads();
    }
#pragma unroll
    for (int i = 0; i < 4; i++)
#pragma unroll
        for (int j = 0; j < 4; j++)
            g_xw[g][(size_t)(rowBase + ty * 4 + i) * NHF + colBase + tx * 4 + j] = acc[i][j];
}

// ---------------- fused GCN aggregation ----------------
__global__ void k_gather(int off, const float* __restrict__ bias) {
    int g = blockIdx.y;
    int n = blockIdx.x * 8 + (threadIdx.x >> 5);
    int lane = threadIdx.x & 31;
    if (n >= NN) return;
    const float4* xw4 = (const float4*)g_xw[g];
    float di = g_dinv[g][n];
    float sn = di * di;
    float4 bb = ((const float4*)bias)[lane];
    float4 sv = xw4[(size_t)n * 32 + lane];
    float ax = bb.x + sn * sv.x, ay = bb.y + sn * sv.y;
    float az = bb.z + sn * sv.z, aw = bb.w + sn * sv.w;
    int e0 = g_rowptr[g][n], e1 = g_rowptr[g][n + 1];
    for (int e = e0; e < e1; e++) {
        int s = g_csrc[g][e];
        float nm = g_cnrm[g][e];
        float4 v = xw4[(size_t)s * 32 + lane];
        ax += nm * v.x; ay += nm * v.y; az += nm * v.z; aw += nm * v.w;
    }
    ax = (ax >= 0.f) ? ax : 0.2f * ax;
    ay = (ay >= 0.f) ? ay : 0.2f * ay;
    az = (az >= 0.f) ? az : 0.2f * az;
    aw = (aw >= 0.f) ? aw : 0.2f * aw;
    float4* o = (float4*)(g_h[g] + (size_t)n * H3 + off);
    o[lane] = make_float4(ax, ay, az, aw);
}

// ---------------- L2 normalize ----------------
__global__ void k_l2() {
    int g = blockIdx.y;
    int warp = blockIdx.x * 8 + (threadIdx.x >> 5);
    int lane = threadIdx.x & 31;
    if (warp >= NN) return;
    const float* hr = g_h[g] + (size_t)warp * H3;
    float ss = 0.f;
#pragma unroll
    for (int t = 0; t < 12; t++) { float v = hr[lane + 32 * t]; ss += v * v; }
    ss = wredsum(ss);
    float inv = 1.f / fmaxf(sqrtf(ss), 1e-12f);
    float* xr = g_x[g] + (size_t)warp * D6;
#pragma unroll
    for (int t = 0; t < 12; t++) xr[lane + 32 * t] = hr[lane + 32 * t] * inv;
}

// ---------------- interaction: 4-row register blocking (counterpart read once per 4 rows) ----------------
__global__ void __launch_bounds__(256) k_interact() {
    int b = blockIdx.x;
    int s1 = g_starts[0][b], e1 = g_starts[0][b + 1];
    int s2 = g_starts[1][b], e2 = g_starts[1][b + 1];
    int n1 = e1 - s1, n2 = e2 - s2;
    int lane = threadIdx.x & 31, w = threadIdx.x >> 5;   // 8 warps
    int g1grp = (n1 + 3) >> 2, g2grp = (n2 + 3) >> 2;
    int totgrp = g1grp + g2grp;
    for (int grp = w; grp < totgrp; grp += 8) {
        bool first = grp < g1grp;
        int t0 = (first ? grp : grp - g1grp) << 2;
        int cnt = (first ? n1 : n2) - t0;               // valid rows in group (1..4)
        const float* srcb = first ? g_x[0] : g_x[1];
        float* outb = first ? g_x[0] : g_x[1];
        int sbase = (first ? s1 : s2) + t0;
        const float* oth = first ? g_x[1] : g_x[0];
        int obase = first ? s2 : s1;
        int ocnt = first ? n2 : n1;
        float sv[4][12], acc[4][12];
#pragma unroll
        for (int r = 0; r < 4; r++) {
            int row = sbase + ((r < cnt) ? r : 0);
            const float* sr = srcb + (size_t)row * D6;
#pragma unroll
            for (int q = 0; q < 12; q++) { sv[r][q] = sr[lane + 32 * q]; acc[r][q] = 0.f; }
        }
        for (int jj = 0; jj < ocnt; jj++) {
            const float* vr = oth + (size_t)(obase + jj) * D6;
            float vv[12];
#pragma unroll
            for (int q = 0; q < 12; q++) vv[q] = vr[lane + 32 * q];
            float p0 = 0.f, p1 = 0.f, p2 = 0.f, p3 = 0.f;
#pragma unroll
            for (int q = 0; q < 12; q++) {
                p0 += sv[0][q] * vv[q];
                p1 += sv[1][q] * vv[q];
                p2 += sv[2][q] * vv[q];
                p3 += sv[3][q] * vv[q];
            }
#pragma unroll
            for (int o = 16; o; o >>= 1) {
                p0 += __shfl_xor_sync(0xffffffffu, p0, o);
                p1 += __shfl_xor_sync(0xffffffffu, p1, o);
                p2 += __shfl_xor_sync(0xffffffffu, p2, o);
                p3 += __shfl_xor_sync(0xffffffffu, p3, o);
            }
#pragma unroll
            for (int q = 0; q < 12; q++) {
                acc[0][q] += p0 * vv[q];
                acc[1][q] += p1 * vv[q];
                acc[2][q] += p2 * vv[q];
                acc[3][q] += p3 * vv[q];
            }
        }
#pragma unroll
        for (int r = 0; r < 4; r++) {
            if (r < cnt) {
                float* orow = outb + (size_t)(sbase + r) * D6 + H3;
#pragma unroll
                for (int q = 0; q < 12; q++) orow[lane + 32 * q] = acc[r][q];
            }
        }
    }
}

// ---------------- cvec + z1pre zero ----------------
__global__ void k_cvec(const float* __restrict__ Wih, const float* __restrict__ Whh,
                       const float* __restrict__ bih, const float* __restrict__ bhh) {
    __shared__ float shv[D6];
    int tid = threadIdx.x, lane = tid & 31, w = tid >> 5;
    for (int j = tid; j < D6; j += 256) {
        float gi = bih[j] + bhh[j];
        float gg = bih[2 * D6 + j] + bhh[2 * D6 + j];
        float go = bih[3 * D6 + j] + bhh[3 * D6 + j];
        float c = sgm(gi) * tanhf(gg);
        shv[j] = sgm(go) * tanhf(c);
    }
    if (blockIdx.x < 256) g_z1pre[blockIdx.x * 256 + tid] = 0.f;
    __syncthreads();
    int gout = blockIdx.x * 8 + w;
    const float* wi = Wih + (size_t)gout * D12;
    const float* wh = Whh + (size_t)gout * D6;
    float p = 0.f;
#pragma unroll
    for (int t = 0; t < 24; t++) {
        int k = lane + 32 * t;
        p += shv[k] * (wi[k] + wh[k]);
    }
    p = wredsum(p);
    if (lane == 0) g_cvec[gout] = bih[gout] + bhh[gout] + p;
}

// ---------------- fused attention step 1 ----------------
__global__ void k_attn1(const float* __restrict__ bih, const float* __restrict__ bhh) {
    __shared__ float hq[D6];
    __shared__ float sc[SMAXSEG];
    __shared__ float red[256];
    int g = blockIdx.y, b = blockIdx.x;
    int tid = threadIdx.x, lane = tid & 31, w = tid >> 5;
    for (int j = tid; j < D6; j += 256) {
        float gi = bih[j] + bhh[j];
        float gg = bih[2 * D6 + j] + bhh[2 * D6 + j];
        float go = bih[3 * D6 + j] + bhh[3 * D6 + j];
        float c = sgm(gi) * tanhf(gg);
        hq[j] = sgm(go) * tanhf(c);
    }
    __syncthreads();
    int s = g_starts[g][b], e = g_starts[g][b + 1], cnt = e - s;
    float* rout = g_rb[g] + (size_t)b * D6;
    if (cnt <= 0) {
        for (int j = tid; j < D6; j += 256) rout[j] = 0.f;
        return;
    }
    const float* x = g_x[g];
    for (int t = w; t < cnt; t += 8) {
        const float* xr = x + (size_t)(s + t) * D6;
        float p = 0.f;
#pragma unroll
        for (int q = 0; q < 24; q++) p += xr[lane + 32 * q] * hq[lane + 32 * q];
        p = wredsum(p);
        if (lane == 0) sc[t] = p;
    }
    __syncthreads();
    float lm = -3.4e38f;
    for (int t = tid; t < cnt; t += 256) lm = fmaxf(lm, sc[t]);
    red[tid] = lm; __syncthreads();
    for (int o = 128; o > 0; o >>= 1) { if (tid < o) red[tid] = fmaxf(red[tid], red[tid + o]); __syncthreads(); }
    float m = red[0]; __syncthreads();
    float ls = 0.f;
    for (int t = tid; t < cnt; t += 256) { float ev = expf(sc[t] - m); sc[t] = ev; ls += ev; }
    red[tid] = ls; __syncthreads();
    for (int o = 128; o > 0; o >>= 1) { if (tid < o) red[tid] += red[tid + o]; __syncthreads(); }
    float inv = 1.f / red[0]; __syncthreads();
    float a0 = 0.f, a1 = 0.f, a2 = 0.f;
    for (int t = 0; t < cnt; t++) {
        float wv = sc[t];
        const float* xr = x + (size_t)(s + t) * D6;
        a0 += wv * xr[tid];
        a1 += wv * xr[tid + 256];
        a2 += wv * xr[tid + 512];
    }
    rout[tid] = a0 * inv;
    rout[tid + 256] = a1 * inv;
    rout[tid + 512] = a2 * inv;
}

// gates2 (64x64; LDS.128 operand fetch)
__global__ void k_gates2(const float* __restrict__ Wih) {
    __shared__ float As[16][64];
    __shared__ float Bs[16][68];
    int g = blockIdx.z;
    int tid = threadIdx.x, tx = tid & 15, ty = tid >> 4;
    int colBase = blockIdx.x * 64, rowBase = blockIdx.y * 64;
    const float* A = g_rb[g];
    const float* B = Wih + D6;
    float acc[4][4] = {};
    for (int k0 = 0; k0 < D6; k0 += 16) {
#pragma unroll
        for (int l = 0; l < 4; l++) {
            int idx = tid + l * 256;
            int m = idx >> 4, kk = idx & 15;
            As[kk][m] = A[(size_t)(rowBase + m) * D6 + k0 + kk];
            Bs[kk][m] = B[(size_t)(colBase + m) * D12 + k0 + kk];
        }
        __syncthreads();
#pragma unroll
        for (int kk = 0; kk < 16; kk++) {
            float4 a4 = *(const float4*)&As[kk][ty * 4];
            float4 b4 = *(const float4*)&Bs[kk][tx * 4];
            float av[4] = { a4.x, a4.y, a4.z, a4.w };
            float bv[4] = { b4.x, b4.y, b4.z, b4.w };
#pragma unroll
            for (int i = 0; i < 4; i++)
#pragma unroll
                for (int j = 0; j < 4; j++) acc[i][j] += av[i] * bv[j];
        }
        __syncthreads();
    }
#pragma unroll
    for (int i = 0; i < 4; i++) {
        int row = rowBase + ty * 4 + i;
#pragma unroll
        for (int j = 0; j < 4; j++) {
            int col = colBase + tx * 4 + j;
            g_gates[g][(size_t)row * G4 + col] = acc[i][j] + g_cvec[col];
        }
    }
}

// ---------------- fused attention step 2 (lstm2 + attention) ----------------
__global__ void k_attn2(const float* __restrict__ bih, const float* __restrict__ bhh) {
    __shared__ float hq[D6];
    __shared__ float sc[SMAXSEG];
    __shared__ float red[256];
    int g = blockIdx.y, b = blockIdx.x;
    int tid = threadIdx.x, lane = tid & 31, w = tid >> 5;
    const float* gt = g_gates[g] + (size_t)b * G4;
    float* zb = g_z + (size_t)b * G4 + (g ? D12 : 0);
    for (int j = tid; j < D6; j += 256) {
        float gi1 = bih[j] + bhh[j];
        float gg1 = bih[2 * D6 + j] + bhh[2 * D6 + j];
        float cv = sgm(gi1) * tanhf(gg1);
        float gi = gt[j], gf = gt[D6 + j], gg = gt[2 * D6 + j], go = gt[3 * D6 + j];
        float c = sgm(gf) * cv + sgm(gi) * tanhf(gg);
        float h = sgm(go) * tanhf(c);
        hq[j] = h;
        zb[j] = h;
    }
    __syncthreads();
    int s = g_starts[g][b], e = g_starts[g][b + 1], cnt = e - s;
    float* rout = zb + D6;
    if (cnt <= 0) {
        for (int j = tid; j < D6; j += 256) rout[j] = 0.f;
        return;
    }
    const float* x = g_x[g];
    for (int t = w; t < cnt; t += 8) {
        const float* xr = x + (size_t)(s + t) * D6;
        float p = 0.f;
#pragma unroll
        for (int q = 0; q < 24; q++) p += xr[lane + 32 * q] * hq[lane + 32 * q];
        p = wredsum(p);
        if (lane == 0) sc[t] = p;
    }
    __syncthreads();
    float lm = -3.4e38f;
    for (int t = tid; t < cnt; t += 256) lm = fmaxf(lm, sc[t]);
    red[tid] = lm; __syncthreads();
    for (int o = 128; o > 0; o >>= 1) { if (tid < o) red[tid] = fmaxf(red[tid], red[tid + o]); __syncthreads(); }
    float m = red[0]; __syncthreads();
    float ls = 0.f;
    for (int t = tid; t < cnt; t += 256) { float ev = expf(sc[t] - m); sc[t] = ev; ls += ev; }
    red[tid] = ls; __syncthreads();
    for (int o = 128; o > 0; o >>= 1) { if (tid < o) red[tid] += red[tid + o]; __syncthreads(); }
    float inv = 1.f / red[0]; __syncthreads();
    float a0 = 0.f, a1 = 0.f, a2 = 0.f;
    for (int t = 0; t < cnt; t++) {
        float wv = sc[t];
        const float* xr = x + (size_t)(s + t) * D6;
        a0 += wv * xr[tid];
        a1 += wv * xr[tid + 256];
        a2 += wv * xr[tid + 512];
    }
    rout[tid] = a0 * inv;
    rout[tid + 256] = a1 * inv;
    rout[tid + 512] = a2 * inv;
}

// ---------------- MLP head ----------------
__global__ void k_mlp1_gemm(const float* __restrict__ Wp1) {
    __shared__ float As[16][64];
    __shared__ float Bs[16][68];
    int tid = threadIdx.x, tx = tid & 15, ty = tid >> 4;
    int colBase = blockIdx.x * 64, rowBase = blockIdx.y * 64;
    int kBase = blockIdx.z * 128;
    float acc[4][4] = {};
    for (int k0 = 0; k0 < 128; k0 += 16) {
#pragma unroll
        for (int l = 0; l < 4; l++) {
            int idx = tid + l * 256;
            int m = idx >> 4, kk = idx & 15;
            As[kk][m] = g_z[(size_t)(rowBase + m) * G4 + kBase + k0 + kk];
            Bs[kk][m] = Wp1[(size_t)(colBase + m) * G4 + kBase + k0 + kk];
        }
        __syncthreads();
#pragma unroll
        for (int kk = 0; kk < 16; kk++) {
            float4 a4 = *(const float4*)&As[kk][ty * 4];
            float4 b4 = *(const float4*)&Bs[kk][tx * 4];
            float av[4] = { a4.x, a4.y, a4.z, a4.w };
            float bv[4] = { b4.x, b4.y, b4.z, b4.w };
#pragma unroll
            for (int i = 0; i < 4; i++)
#pragma unroll
                for (int j = 0; j < 4; j++) acc[i][j] += av[i] * bv[j];
        }
        __syncthreads();
    }
#pragma unroll
    for (int i = 0; i < 4; i++)
#pragma unroll
        for (int j = 0; j < 4; j++)
            atomicAdd(&g_z1pre[(size_t)(rowBase + ty * 4 + i) * 256 + colBase + tx * 4 + j],
                      acc[i][j]);
}
__global__ void k_mlp2(const float* __restrict__ bp1,
                       const float* __restrict__ Wp2, const float* __restrict__ bp2) {
    int gw = (blockIdx.x * blockDim.x + threadIdx.x) >> 5;
    int lane = threadIdx.x & 31;
    if (gw >= NB * 128) return;
    int b = gw >> 7, o = gw & 127;
    const float* zp = g_z1pre + (size_t)b * 256;
    const float* wr = Wp2 + (size_t)o * 256;
    float p = 0.f;
#pragma unroll
    for (int k = lane; k < 256; k += 32) {
        float zv = fmaxf(zp[k] + bp1[k], 0.f);
        p += zv * wr[k];
    }
    p = wredsum(p);
    if (lane == 0) g_z2[(size_t)b * 128 + o] = fmaxf(p + bp2[o], 0.f);
}
__global__ void k_final(const float* __restrict__ Wp3, const float* __restrict__ bp3,
                        float* __restrict__ out) {
    int b = blockIdx.x * blockDim.x + threadIdx.x;
    if (b >= NB) return;
    float p = bp3[0];
#pragma unroll 16
    for (int k = 0; k < 128; k++) p += g_z2[(size_t)b * 128 + k] * Wp3[k];
    out[b] = 1.f / (1.f + expf(-p));
}

// ---------------- launch sequence ----------------
extern "C" void kernel_launch(void* const* d_in, const int* in_sizes, int n_in,
                              void* d_out, int out_size) {
    const float* f1 = (const float*)d_in[0];
    const float* f2 = (const float*)d_in[1];
    const float* ea1 = (const float*)d_in[2];
    const float* ea2 = (const float*)d_in[3];
    const float* W[3]  = { (const float*)d_in[4], (const float*)d_in[6], (const float*)d_in[8] };
    const float* bW[3] = { (const float*)d_in[5], (const float*)d_in[7], (const float*)d_in[9] };
    const float* Wih = (const float*)d_in[10];
    const float* bih = (const float*)d_in[11];
    const float* Whh = (const float*)d_in[12];
    const float* bhh = (const float*)d_in[13];
    const float* Wp1 = (const float*)d_in[14];
    const float* bp1 = (const float*)d_in[15];
    const float* Wp2 = (const float*)d_in[16];
    const float* bp2 = (const float*)d_in[17];
    const float* Wp3 = (const float*)d_in[18];
    const float* bp3 = (const float*)d_in[19];
    const int* ei1 = (const int*)d_in[20];
    const int* ei2 = (const int*)d_in[21];
    const int* b1 = (const int*)d_in[22];
    const int* b2 = (const int*)d_in[23];
    float* out = (float*)d_out;

    static cudaStream_t s1 = (cudaStream_t)0;
    static cudaEvent_t evA, evB;
    static bool inited = false;
    if (!inited) {
        cudaStreamCreateWithFlags(&s1, cudaStreamNonBlocking);
        cudaEventCreateWithFlags(&evA, cudaEventDisableTiming);
        cudaEventCreateWithFlags(&evB, cudaEventDisableTiming);
        inited = true;
    }
    cudaStream_t s0 = (cudaStream_t)0;
    const int T = 256;

    // side stream: CSR build overlapped with cvec + layer-0 GEMM on s0
    cudaEventRecord(evA, s0);
    cudaStreamWaitEvent(s1, evA, 0);
    k_prep<<<2 * NN / T, T, 0, s1>>>();
    k_count<<<dim3(NE / T, 2), T, 0, s1>>>(ei1, ea1, ei2, ea2);
    k_scan<<<2, 1024, 0, s1>>>();
    k_startsdinv<<<dim3(NN / T, 2), T, 0, s1>>>(b1, b2);
    k_fill<<<dim3(NE / T, 2), T, 0, s1>>>(ei1, ea1, ei2, ea2);
    cudaEventRecord(evB, s1);

    k_cvec<<<G4 / 8, T, 0, s0>>>(Wih, Whh, bih, bhh);
    k_gemm_xw<<<dim3(2, NN / 64, 2), T, 0, s0>>>(f1, f2, 0, W[0]);

    // join: gather needs CSR
    cudaStreamWaitEvent(s0, evB, 0);
    k_gather<<<dim3(NN / 8, 2), T, 0, s0>>>(0, bW[0]);
    for (int l = 1; l < 3; l++) {
        k_gemm_xw<<<dim3(2, NN / 64, 2), T, 0, s0>>>(f1, f2, l, W[l]);
        k_gather<<<dim3(NN / 8, 2), T, 0, s0>>>(l * NHF, bW[l]);
    }
    k_l2<<<dim3(NN / 8, 2), T, 0, s0>>>();
    k_interact<<<NB, T, 0, s0>>>();

    k_attn1<<<dim3(NB, 2), T, 0, s0>>>(bih, bhh);
    k_gates2<<<dim3(G4 / 64, NB / 64, 2), T, 0, s0>>>(Wih);
    k_attn2<<<dim3(NB, 2), T, 0, s0>>>(bih, bhh);

    k_mlp1_gemm<<<dim3(4, 4, 24), T, 0, s0>>>(Wp1);
    k_mlp2<<<(NB * 128 * 32) / T, T, 0, s0>>>(bp1, Wp2, bp2);
    k_final<<<1, T, 0, s0>>>(Wp3, bp3, out);
}